// round 5
// baseline (speedup 1.0000x reference)
#include <cuda_runtime.h>
#include <math.h>

// Problem constants
#define BB  64
#define TT  512
#define II  256
#define OO  1024
#define MM  8
#define IMD 2048

// Persistent-kernel configuration
#define NB   128            // persistent blocks (<= SM count -> co-resident)
#define NTH  256
#define TK   32             // K-chunk
#define NCOL 3072           // 2048 rec cols + 1024 act cols
#define RECTILES 32         // rec: 2048/64
#define RECCH 2304          // 32 tiles * 72 chunks  (K = 256+2048 = 2304)
#define TOTCH 2944          // + 16 tiles * 40 chunks (K = 256+1024 = 1280)
#define CPB  23             // chunks per block (2944/128, exact)
#define NSLOT 5             // max split-K owners per tile

static_assert(NB * CPB == TOTCH, "balanced split");

// ---------------------------------------------------------------------------
// Device state (allocation-free)
// ---------------------------------------------------------------------------
__device__ __align__(16) float g_xp[2][BB * IMD];        // x_pred ping-pong
__device__ __align__(16) float g_h[BB * OO];             // hidden state
__device__ __align__(16) float g_lse[2][IMD];            // batch-axis logsumexp
__device__ __align__(16) float g_gate[BB * MM];          // gate per (b,m)
__device__ __align__(16) float g_part[NSLOT][BB * NCOL]; // split-K partials
__device__ unsigned g_arrive;
__device__ volatile unsigned g_release;

// ---------------------------------------------------------------------------
__global__ void init_kernel() {
    int i = blockIdx.x * blockDim.x + threadIdx.x;
    int n = gridDim.x * blockDim.x;
    for (int j = i; j < BB * IMD; j += n) g_xp[0][j] = 0.f;
    for (int j = i; j < BB * OO;  j += n) g_h[j] = 0.f;
    for (int j = i; j < IMD;      j += n) g_lse[0][j] = logf((float)BB);
    if (i == 0) { g_arrive = 0u; g_release = 0u; }
}

// Grid-wide barrier (all NB blocks resident by construction)
__device__ __forceinline__ void gbar(unsigned gen) {
    __syncthreads();
    if (threadIdx.x == 0) {
        __threadfence();
        unsigned v = atomicAdd(&g_arrive, 1u);
        if (v == gen * NB + (NB - 1u)) {
            g_release = gen + 1u;
        } else {
            while (g_release <= gen) { __nanosleep(64); }
        }
    }
    __syncthreads();
}

// tile id -> first chunk of that tile
__device__ __forceinline__ int tile_first_chunk(int tile) {
    return (tile < RECTILES) ? tile * 72 : RECCH + (tile - RECTILES) * 40;
}

// Decode chunk -> per-thread global load pointers (2 float4 A, 2 float4 W)
__device__ __forceinline__ void chunk_src(
    int c, int t, int cur,
    const float* __restrict__ x, const float* __restrict__ W_in,
    const float* __restrict__ W_h, const float* __restrict__ W_ir,
    const float* __restrict__ W_hr,
    int lrow, int lcq,
    const float4*& a0, const float4*& a1,
    const float4*& w0, const float4*& w1, bool& cg)
{
    bool rec; int tloc, kc;
    if (c < RECCH) { rec = true;  tloc = c / 72;            kc = c - tloc * 72; }
    else           { rec = false; tloc = (c - RECCH) / 40;  kc = (c - RECCH) - tloc * 40; }
    const int n0 = tloc * 64;
    const int k0 = kc * TK;
    const float* Ap; const float* Wp;
    if (k0 < II) {
        Ap = x + ((size_t)lrow * TT + t) * II + k0;
        Wp = (rec ? W_ir : W_in) + (size_t)(n0 + lrow) * II + k0;
        cg = false;
    } else {
        const int kk = k0 - II;
        if (rec) { Ap = g_xp[cur] + (size_t)lrow * IMD + kk;
                   Wp = W_hr + (size_t)(n0 + lrow) * IMD + kk; }
        else     { Ap = g_h + (size_t)lrow * OO + kk;
                   Wp = W_h + (size_t)(n0 + lrow) * OO + kk; }
        cg = true;
    }
    a0 = (const float4*)(Ap + lcq);
    a1 = (const float4*)(Ap + lcq + 4);
    w0 = (const float4*)(Wp + lcq);
    w1 = (const float4*)(Wp + lcq + 4);
}

// ---------------------------------------------------------------------------
// The whole scan in one kernel. Per step:
//   P1: balanced split-K GEMM partials (+ dot/gate jobs)  | barrier
//   P2: reduce partials, bias+tanh, gate-blend, write ys  | barrier
//   P3: batch-axis LSE of fresh x_pred                    | barrier
// ---------------------------------------------------------------------------
__global__ void __launch_bounds__(NTH) rnn_persistent(
    const float* __restrict__ x,
    const float* __restrict__ W_in, const float* __restrict__ b_in,
    const float* __restrict__ W_h,
    const float* __restrict__ W_ir, const float* __restrict__ b_ir,
    const float* __restrict__ W_hr,
    const float* __restrict__ periods, const float* __restrict__ shifts,
    float* __restrict__ ys, float* __restrict__ hfin, float* __restrict__ ps)
{
    __shared__ float As[64][33];
    __shared__ float Wsm[64][33];
    __shared__ float sred[8];

    const int tid  = threadIdx.x;
    const int bid  = blockIdx.x;
    const int lrow = tid >> 2;          // loader row 0..63
    const int lcq  = (tid & 3) * 8;     // loader col group {0,8,16,24}
    const int br   = tid & 15;          // batches {br, br+16, br+32, br+48}
    const int oc   = tid >> 4;          // outputs {oc, oc+16, oc+32, oc+48}

    unsigned gen = 0;
    for (int t = 0; t < TT; t++) {
        const int cur = t & 1, nxt = cur ^ 1;

        // ================= P1: GEMM =================
        const int c0 = bid * CPB, c1 = c0 + CPB;
        float acc[4][4];
        int cur_tile = -1;

        float4 A0, A1, V0, V1;
        {
            const float4 *pa0, *pa1, *pw0, *pw1; bool cg;
            chunk_src(c0, t, cur, x, W_in, W_h, W_ir, W_hr, lrow, lcq,
                      pa0, pa1, pw0, pw1, cg);
            if (cg) { A0 = __ldcg(pa0); A1 = __ldcg(pa1); }
            else    { A0 = *pa0;        A1 = *pa1; }
            V0 = *pw0; V1 = *pw1;
        }

        for (int c = c0; c < c1; c++) {
            const int gtile = (c < RECCH) ? (c / 72)
                                          : (RECTILES + (c - RECCH) / 40);
            if (gtile != cur_tile) {
                if (cur_tile >= 0) {
                    const int fc = tile_first_chunk(cur_tile);
                    float* dst = g_part[bid - fc / CPB];
                    const int gcol0 = cur_tile * 64;
                    #pragma unroll
                    for (int i = 0; i < 4; i++)
                        #pragma unroll
                        for (int j = 0; j < 4; j++)
                            dst[(br + 16 * i) * NCOL + gcol0 + oc + 16 * j] = acc[i][j];
                }
                #pragma unroll
                for (int i = 0; i < 4; i++)
                    #pragma unroll
                    for (int j = 0; j < 4; j++) acc[i][j] = 0.f;
                cur_tile = gtile;
            }

            __syncthreads();
            As[lrow][lcq + 0] = A0.x; As[lrow][lcq + 1] = A0.y;
            As[lrow][lcq + 2] = A0.z; As[lrow][lcq + 3] = A0.w;
            As[lrow][lcq + 4] = A1.x; As[lrow][lcq + 5] = A1.y;
            As[lrow][lcq + 6] = A1.z; As[lrow][lcq + 7] = A1.w;
            Wsm[lrow][lcq + 0] = V0.x; Wsm[lrow][lcq + 1] = V0.y;
            Wsm[lrow][lcq + 2] = V0.z; Wsm[lrow][lcq + 3] = V0.w;
            Wsm[lrow][lcq + 4] = V1.x; Wsm[lrow][lcq + 5] = V1.y;
            Wsm[lrow][lcq + 6] = V1.z; Wsm[lrow][lcq + 7] = V1.w;
            __syncthreads();

            if (c + 1 < c1) {   // prefetch next chunk under the inner loop
                const float4 *pa0, *pa1, *pw0, *pw1; bool cg;
                chunk_src(c + 1, t, cur, x, W_in, W_h, W_ir, W_hr, lrow, lcq,
                          pa0, pa1, pw0, pw1, cg);
                if (cg) { A0 = __ldcg(pa0); A1 = __ldcg(pa1); }
                else    { A0 = *pa0;        A1 = *pa1; }
                V0 = *pw0; V1 = *pw1;
            }

            #pragma unroll
            for (int k = 0; k < TK; k++) {
                float a0 = As[br][k],      a1 = As[br + 16][k];
                float a2 = As[br + 32][k], a3 = As[br + 48][k];
                float w0 = Wsm[oc][k],      w1 = Wsm[oc + 16][k];
                float w2 = Wsm[oc + 32][k], w3 = Wsm[oc + 48][k];
                acc[0][0] += a0 * w0; acc[0][1] += a0 * w1;
                acc[0][2] += a0 * w2; acc[0][3] += a0 * w3;
                acc[1][0] += a1 * w0; acc[1][1] += a1 * w1;
                acc[1][2] += a1 * w2; acc[1][3] += a1 * w3;
                acc[2][0] += a2 * w0; acc[2][1] += a2 * w1;
                acc[2][2] += a2 * w2; acc[2][3] += a2 * w3;
                acc[3][0] += a3 * w0; acc[3][1] += a3 * w1;
                acc[3][2] += a3 * w2; acc[3][3] += a3 * w3;
            }
        }
        {   // final flush
            const int fc = tile_first_chunk(cur_tile);
            float* dst = g_part[bid - fc / CPB];
            const int gcol0 = cur_tile * 64;
            #pragma unroll
            for (int i = 0; i < 4; i++)
                #pragma unroll
                for (int j = 0; j < 4; j++)
                    dst[(br + 16 * i) * NCOL + gcol0 + oc + 16 * j] = acc[i][j];
        }

        // ---- P1b: surprisal dot -> gate (uses PREVIOUS step's xp & lse) ----
        for (int d = bid; d < BB * MM; d += NB) {
            const int b = d >> 3, m = d & 7;
            float xv  = x[((size_t)b * TT + t) * II + tid];
            float xpv = __ldcg(&g_xp[cur][b * IMD + m * II + tid]);
            float lsv = __ldcg(&g_lse[cur][m * II + tid]);
            float part = (xpv - lsv) * xv;
            #pragma unroll
            for (int off = 16; off; off >>= 1)
                part += __shfl_xor_sync(0xffffffffu, part, off);
            if ((tid & 31) == 0) sred[tid >> 5] = part;
            __syncthreads();
            if (tid == 0) {
                float tot = 0.f;
                #pragma unroll
                for (int w = 0; w < 8; w++) tot += sred[w];
                float mp = tot * (1.0f / II) * periods[m];
                float gate = (sinf((float)t * mp + shifts[m]) + 1.f) * 0.5f;
                g_gate[d] = gate;
                ps[((size_t)b * TT + t) * MM + m] = mp;
            }
            __syncthreads();
        }

        gbar(gen++);

        // ================= P2: reduce + activate + blend =================
        #pragma unroll
        for (int q = 0; q < 6; q++) {
            const int idx = q * (NB * NTH) + bid * NTH + tid; // < 196608
            const int b   = idx / NCOL;
            const int col = idx - b * NCOL;
            const int tile = col >> 6;
            const int fc = tile_first_chunk(tile);
            const int lc = fc + ((tile < RECTILES) ? 71 : 39);
            const int ns = lc / CPB - fc / CPB;      // slots-1
            float s = 0.f;
            for (int sl = 0; sl <= ns; sl++)
                s += __ldcg(&g_part[sl][b * NCOL + col]);
            if (col < IMD) {
                g_xp[nxt][b * IMD + col] = tanhf(s + b_ir[col]);
            } else {
                const int o = col - IMD;
                float a  = tanhf(s + b_in[o]);
                float gt = __ldcg(&g_gate[b * MM + (o >> 7)]);
                float hv = __ldcg(&g_h[b * OO + o]);
                float y  = (1.f - gt) * a + gt * hv;
                g_h[b * OO + o] = y;
                ys[((size_t)b * TT + t) * OO + o] = y;
            }
        }

        gbar(gen++);

        // ================= P3: batch-axis logsumexp of xp[nxt] ============
        {
            const int w = bid * (NTH / 32) + (tid >> 5);    // 0..1023
            const int lane = tid & 31;
            for (int col = w; col < IMD; col += NB * (NTH / 32)) {
                float v0 = __ldcg(&g_xp[nxt][lane * IMD + col]);
                float v1 = __ldcg(&g_xp[nxt][(lane + 32) * IMD + col]);
                float mx = fmaxf(v0, v1);
                #pragma unroll
                for (int off = 16; off; off >>= 1)
                    mx = fmaxf(mx, __shfl_xor_sync(0xffffffffu, mx, off));
                float sum = expf(v0 - mx) + expf(v1 - mx);
                #pragma unroll
                for (int off = 16; off; off >>= 1)
                    sum += __shfl_xor_sync(0xffffffffu, sum, off);
                if (lane == 0) g_lse[nxt][col] = mx + logf(sum);
            }
        }

        gbar(gen++);
    }

    // h_final -> output (everything visible after last barrier)
    for (int idx = bid * NTH + tid; idx < BB * OO; idx += NB * NTH)
        hfin[idx] = __ldcg(&g_h[idx]);
}

// ---------------------------------------------------------------------------
// 2 graph nodes total. Inputs (metadata order):
//   x, W_in, b_in, W_h, W_ir, b_ir, W_hr, module_periods, module_shifts
// Output: concat(ys [B,T,O], h_final [B,O], ps [B,T,M]) fp32
// ---------------------------------------------------------------------------
extern "C" void kernel_launch(void* const* d_in, const int* in_sizes, int n_in,
                              void* d_out, int out_size) {
    const float* x       = (const float*)d_in[0];
    const float* W_in    = (const float*)d_in[1];
    const float* b_in    = (const float*)d_in[2];
    const float* W_h     = (const float*)d_in[3];
    const float* W_ir    = (const float*)d_in[4];
    const float* b_ir    = (const float*)d_in[5];
    const float* W_hr    = (const float*)d_in[6];
    const float* periods = (const float*)d_in[7];
    const float* shifts  = (const float*)d_in[8];

    float* out  = (float*)d_out;
    float* ys   = out;                                  // [B,T,O]
    float* hfin = out + (size_t)BB * TT * OO;           // [B,O]
    float* ps   = hfin + (size_t)BB * OO;               // [B,T,M]

    init_kernel<<<256, 256>>>();
    rnn_persistent<<<NB, NTH>>>(x, W_in, b_in, W_h, W_ir, b_ir, W_hr,
                                periods, shifts, ys, hfin, ps);
}